// round 15
// baseline (speedup 1.0000x reference)
#include <cuda_runtime.h>

// Problem constants
#define N_PTS   16384
#define M_REF   4096
#define L_LAYERS 8
#define KMAX    3                    // Fourier order; empirically rel_err ~3e-6
#define RNK     (2*KMAX + 1)         // 7 features per coordinate
#define RPAD    8                    // padded row (2 x float4)
#define R2      (RNK*RNK)            // 49
#define SPAD    (RNK*RPAD)           // 56
#define EPAD    64                   // padded element stride (coalesced, pow2)
#define PBLK    32                   // producer blocks (S partials)
#define MPB     (M_REF / PBLK)       // 128 reference points per producer block
#define K1TPB   256                  // prep block size
#define TPB     128                  // final block size
#define NBLK    (N_PTS / TPB)        // 128 final blocks
#define SCALE   4.4711032452e-6f     // exp(-4) / 4096

// Scratch (device global; fully rewritten every call)
// g_Spart layout [p][e]: producer block p's 49 S-elements (stride 64).
__device__ float g_Spart[PBLK * EPAD];

// c_0 = I_0(2), c_k = 2*I_k(2)
__constant__ float C_BES[KMAX + 1] = {
    2.27958530f, 3.18127371f, 1.37789690f, 0.42547992f
};

__device__ __forceinline__ float ex2_approx(float d) {
    float r; asm("ex2.approx.ftz.f32 %0, %1;" : "=f"(r) : "f"(d)); return r;
}
__device__ __forceinline__ float rcp_approx(float d) {
    float r; asm("rcp.approx.ftz.f32 %0, %1;" : "=f"(r) : "f"(d)); return r;
}
// tanh via e^{2x}: 1 - 2/(e^{2x}+1). Saturates correctly. Rel err ~1e-6.
__device__ __forceinline__ float fast_tanh(float x) {
    float e = ex2_approx(x * 2.8853900817779268f);
    return fmaf(-2.0f, rcp_approx(e + 1.0f), 1.0f);
}

// Fourier features via MUFU sin/cos + Chebyshev recurrence.
// out[0]=w0; out[k]=w_k cos(k a); out[KMAX+k]=w_k sin(k a), k=1..KMAX.
template <bool WEIGHTED>
__device__ __forceinline__ void four_feats(float ang, float* out, float wscale) {
    float s = __sinf(ang);
    float c = __cosf(ang);
    float c2 = 2.0f * c;
    float ckm = 1.0f, skm = 0.0f;
    float ck  = c,    sk  = s;
    out[0] = WEIGHTED ? C_BES[0] * wscale : 1.0f;
    #pragma unroll
    for (int k = 1; k <= KMAX; k++) {
        float w = WEIGHTED ? C_BES[k] * wscale : 1.0f;
        out[k]        = w * ck;
        out[KMAX + k] = w * sk;
        float cn = fmaf(c2, ck, -ckm);
        float sn = fmaf(c2, sk, -skm);
        ckm = ck; skm = sk; ck = cn; sk = sn;
    }
}

// -------------------------------------------------------------------------
// Kernel 1: 32 producer blocks x 256 threads. Partial S matrices over 128
// reference points each -> g_Spart[b][*] (coalesced row store).
// -------------------------------------------------------------------------
__global__ void __launch_bounds__(K1TPB) prep_kernel(
    const float* __restrict__ refset)
{
    __shared__ __align__(16) float V0[MPB * RNK];
    __shared__ __align__(16) float V1[MPB * RNK];

    const int b   = blockIdx.x;
    const int tid = threadIdx.x;

    if (tid < MPB) {
        int m = b * MPB + tid;
        float2 g = ((const float2*)refset)[m];
        float v0[RNK], v1[RNK];
        four_feats<true>(g.x, v0, SCALE);   // e^-4/M folded into v0
        four_feats<true>(g.y, v1, 1.0f);
        #pragma unroll
        for (int i = 0; i < RNK; i++) {
            V0[tid * RNK + i] = v0[i];
            V1[tid * RNK + i] = v1[i];
        }
    }
    __syncthreads();

    if (tid < R2) {
        int j = tid / RNK, k = tid - (tid / RNK) * RNK;
        float a0 = 0.f, a1 = 0.f, a2 = 0.f, a3 = 0.f;
        #pragma unroll 4
        for (int mm = 0; mm < MPB; mm += 4) {
            a0 = fmaf(V0[(mm + 0) * RNK + j], V1[(mm + 0) * RNK + k], a0);
            a1 = fmaf(V0[(mm + 1) * RNK + j], V1[(mm + 1) * RNK + k], a1);
            a2 = fmaf(V0[(mm + 2) * RNK + j], V1[(mm + 2) * RNK + k], a2);
            a3 = fmaf(V0[(mm + 3) * RNK + j], V1[(mm + 3) * RNK + k], a3);
        }
        // Coalesced row store: consecutive threads -> consecutive floats
        g_Spart[b * EPAD + tid] = (a0 + a1) + (a2 + a3);
    }
}

// -------------------------------------------------------------------------
// Kernel 2: 128 blocks x 128 threads. One n per thread.
//   Coalesced column reduce (32 LDG.32, tid<49) with the 8-layer tanh chain
//   + trig computed in its latency shadow (x is a warm harness input — no
//   cross-kernel g_feats round trip). Then 7x2-float4 bilinear, MLP, softmax.
// -------------------------------------------------------------------------
__global__ void __launch_bounds__(TPB) final_kernel(
    const float* __restrict__ x,
    const float* __restrict__ layer_W,
    const float* __restrict__ layer_b,
    const float* __restrict__ layer_scale,
    const float* __restrict__ layer_shift,
    const float* __restrict__ W1,
    const float* __restrict__ b1,
    const float* __restrict__ W2,
    const float* __restrict__ b2,
    float* __restrict__ out)
{
    __shared__ __align__(16) float S[SPAD];   // 7 rows x 8 (pad col = 0)

    const int tid = threadIdx.x;
    const int n   = blockIdx.x * TPB + tid;

    // Issue input load immediately
    float2 xin = ((const float2*)x)[n];

    // ---- coalesced column reduce: 32 LDG.32 per thread, 4 accumulators ----
    if (tid < R2) {
        const float* src = g_Spart + tid;
        float a0 = 0.f, a1 = 0.f, a2 = 0.f, a3 = 0.f;
        #pragma unroll
        for (int p = 0; p < PBLK; p += 4) {
            a0 += src[(p + 0) * EPAD];
            a1 += src[(p + 1) * EPAD];
            a2 += src[(p + 2) * EPAD];
            a3 += src[(p + 3) * EPAD];
        }
        int j = tid / RNK, k = tid - (tid / RNK) * RNK;
        S[j * RPAD + k] = (a0 + a1) + (a2 + a3);
    } else if (tid < R2 + RNK) {
        int j = tid - R2;                       // 7 pad slots (col 7)
        S[j * RPAD + (RPAD - 1)] = 0.0f;
    }

    // ---- 8-layer tanh chain (pure ALU; overlaps the reduce LDG latency) --
    float h0 = xin.x, h1 = xin.y;
    #pragma unroll
    for (int l = 0; l < L_LAYERS; l++) {
        float w00 = layer_W[l * 4 + 0], w01 = layer_W[l * 4 + 1];
        float w10 = layer_W[l * 4 + 2], w11 = layer_W[l * 4 + 3];
        float c0  = layer_b[l * 2 + 0],  c1  = layer_b[l * 2 + 1];
        float sc0 = layer_scale[l * 2 + 0], sc1 = layer_scale[l * 2 + 1];
        float t0  = layer_shift[l * 2 + 0], t1  = layer_shift[l * 2 + 1];
        float u0 = fast_tanh(fmaf(h0, w00, fmaf(h1, w01, c0)));
        float u1 = fast_tanh(fmaf(h0, w10, fmaf(h1, w11, c1)));
        h0 = fmaf(u0, sc0, t0);
        h1 = fmaf(u1, sc1, t1);
    }

    float u0[RNK];
    __align__(16) float u1[RPAD];
    four_feats<false>(h0, u0, 1.0f);
    four_feats<false>(h1, u1, 1.0f);
    u1[RPAD - 1] = 0.0f;

    __syncthreads();

    // ---- bilinear form u0^T S u1 (7 rows x 2 float4) ----
    const float4* u1v = (const float4*)u1;
    float agg = 0.0f;
    #pragma unroll
    for (int j = 0; j < RNK; j++) {
        const float4* Sv = (const float4*)(S + j * RPAD);
        float4 s0 = Sv[0], s1 = Sv[1];
        float4 w0 = u1v[0], w1 = u1v[1];
        float t0 = fmaf(s0.x, w0.x, s1.x * w1.x);
        float t1 = fmaf(s0.y, w0.y, s1.y * w1.y);
        float t2 = fmaf(s0.z, w0.z, s1.z * w1.z);
        float t3 = fmaf(s0.w, w0.w, s1.w * w1.w);
        agg = fmaf(u0[j], (t0 + t1) + (t2 + t3), agg);
    }

    // ---- tiny MLP + 2-way softmax (logits bounded -> no max-sub) ----
    float hh[4];
    #pragma unroll
    for (int j = 0; j < 4; j++)
        hh[j] = fast_tanh(fmaf(agg, W1[j], b1[j]));

    float l0 = b2[0], l1 = b2[1];
    #pragma unroll
    for (int j = 0; j < 4; j++) {
        l0 = fmaf(W2[j],     hh[j], l0);
        l1 = fmaf(W2[4 + j], hh[j], l1);
    }

    const float LOG2E = 1.4426950408889634f;
    float e0 = ex2_approx(l0 * LOG2E);
    float e1 = ex2_approx(l1 * LOG2E);
    float inv = rcp_approx(e0 + e1);
    ((float2*)out)[n] = make_float2(e0 * inv, e1 * inv);
}

// -------------------------------------------------------------------------
extern "C" void kernel_launch(void* const* d_in, const int* in_sizes, int n_in,
                              void* d_out, int out_size)
{
    const float* x           = (const float*)d_in[0];
    const float* layer_W     = (const float*)d_in[1];
    const float* layer_b     = (const float*)d_in[2];
    const float* layer_scale = (const float*)d_in[3];
    const float* layer_shift = (const float*)d_in[4];
    const float* refset      = (const float*)d_in[5];
    const float* W1          = (const float*)d_in[6];
    const float* b1          = (const float*)d_in[7];
    const float* W2          = (const float*)d_in[8];
    const float* b2          = (const float*)d_in[9];
    float* out = (float*)d_out;

    prep_kernel<<<PBLK, K1TPB>>>(refset);
    final_kernel<<<NBLK, TPB>>>(x, layer_W, layer_b, layer_scale, layer_shift,
                                W1, b1, W2, b2, out);
}

// round 16
// speedup vs baseline: 1.2316x; 1.2316x over previous
#include <cuda_runtime.h>

// Problem constants
#define N_PTS   16384
#define M_REF   4096
#define L_LAYERS 8
#define KMAX    3                    // Fourier order; sqrt(M)-averaged trunc err ~3e-6
#define RNK     (2*KMAX + 1)         // 7 features per coordinate
#define RPAD    8                    // padded row (2 x float4)
#define R2      (RNK*RNK)            // 49
#define SPAD    (RNK*RPAD)           // 56
#define EPAD    64                   // padded element stride (coalesced, pow2)
#define PBLK    32                   // producer blocks (S partials)
#define MPB     (M_REF / PBLK)       // 128 reference points per producer block
#define K1TPB   256                  // kernel-1 block size
#define FBLK    (N_PTS / K1TPB)      // 64 feats blocks in kernel 1
#define TPB     128                  // kernel-2 block size
#define NBLK    (N_PTS / TPB)        // 128 kernel-2 blocks
#define SCALE   4.4711032452e-6f     // exp(-4) / 4096

// Scratch (device globals; fully rewritten every call)
// g_Spart layout [p][e]: producer block p's 49 S-elements (stride 64).
__device__ float  g_Spart[PBLK * EPAD];
__device__ float2 g_feats[N_PTS];

// c_0 = I_0(2), c_k = 2*I_k(2)
__constant__ float C_BES[KMAX + 1] = {
    2.27958530f, 3.18127371f, 1.37789690f, 0.42547992f
};

__device__ __forceinline__ float ex2_approx(float d) {
    float r; asm("ex2.approx.ftz.f32 %0, %1;" : "=f"(r) : "f"(d)); return r;
}
__device__ __forceinline__ float rcp_approx(float d) {
    float r; asm("rcp.approx.ftz.f32 %0, %1;" : "=f"(r) : "f"(d)); return r;
}
// tanh via e^{2x}: 1 - 2/(e^{2x}+1). Saturates correctly. Rel err ~1e-6.
__device__ __forceinline__ float fast_tanh(float x) {
    float e = ex2_approx(x * 2.8853900817779268f);
    return fmaf(-2.0f, rcp_approx(e + 1.0f), 1.0f);
}

// Fourier features via MUFU sin/cos + Chebyshev recurrence.
// out[0]=w0; out[k]=w_k cos(k a); out[KMAX+k]=w_k sin(k a), k=1..KMAX.
template <bool WEIGHTED>
__device__ __forceinline__ void four_feats(float ang, float* out, float wscale) {
    float s = __sinf(ang);
    float c = __cosf(ang);
    float c2 = 2.0f * c;
    float ckm = 1.0f, skm = 0.0f;
    float ck  = c,    sk  = s;
    out[0] = WEIGHTED ? C_BES[0] * wscale : 1.0f;
    #pragma unroll
    for (int k = 1; k <= KMAX; k++) {
        float w = WEIGHTED ? C_BES[k] * wscale : 1.0f;
        out[k]        = w * ck;
        out[KMAX + k] = w * sk;
        float cn = fmaf(c2, ck, -ckm);
        float sn = fmaf(c2, sk, -skm);
        ckm = ck; skm = sk; ck = cn; sk = sn;
    }
}

// -------------------------------------------------------------------------
// Kernel 1: 96 blocks x 256 threads, two disjoint roles:
//   blocks [0,32):   S-partial producers (128 refs each) -> g_Spart[b][*]
//   blocks [32,96):  8-layer tanh chain for 256 n's each -> g_feats
// Both outputs consumed only after the launch boundary.
// -------------------------------------------------------------------------
__global__ void __launch_bounds__(K1TPB) prep_kernel(
    const float* __restrict__ refset,
    const float* __restrict__ x,
    const float* __restrict__ layer_W,
    const float* __restrict__ layer_b,
    const float* __restrict__ layer_scale,
    const float* __restrict__ layer_shift)
{
    const int b   = blockIdx.x;
    const int tid = threadIdx.x;

    if (b < PBLK) {
        // ---------------- S-partial producer ----------------
        __shared__ __align__(16) float V0[MPB * RNK];
        __shared__ __align__(16) float V1[MPB * RNK];

        if (tid < MPB) {
            int m = b * MPB + tid;
            float2 g = ((const float2*)refset)[m];
            float v0[RNK], v1[RNK];
            four_feats<true>(g.x, v0, SCALE);   // e^-4/M folded into v0
            four_feats<true>(g.y, v1, 1.0f);
            #pragma unroll
            for (int i = 0; i < RNK; i++) {
                V0[tid * RNK + i] = v0[i];
                V1[tid * RNK + i] = v1[i];
            }
        }
        __syncthreads();

        if (tid < R2) {
            int j = tid / RNK, k = tid - (tid / RNK) * RNK;
            float a0 = 0.f, a1 = 0.f, a2 = 0.f, a3 = 0.f;
            #pragma unroll 4
            for (int mm = 0; mm < MPB; mm += 4) {
                a0 = fmaf(V0[(mm + 0) * RNK + j], V1[(mm + 0) * RNK + k], a0);
                a1 = fmaf(V0[(mm + 1) * RNK + j], V1[(mm + 1) * RNK + k], a1);
                a2 = fmaf(V0[(mm + 2) * RNK + j], V1[(mm + 2) * RNK + k], a2);
                a3 = fmaf(V0[(mm + 3) * RNK + j], V1[(mm + 3) * RNK + k], a3);
            }
            // Coalesced row store: consecutive threads -> consecutive floats
            g_Spart[b * EPAD + tid] = (a0 + a1) + (a2 + a3);
        }
    } else {
        // ---------------- tanh-chain feats ----------------
        int n = (b - PBLK) * K1TPB + tid;
        float2 xin = ((const float2*)x)[n];
        float h0 = xin.x, h1 = xin.y;
        #pragma unroll
        for (int l = 0; l < L_LAYERS; l++) {
            float w00 = layer_W[l * 4 + 0], w01 = layer_W[l * 4 + 1];
            float w10 = layer_W[l * 4 + 2], w11 = layer_W[l * 4 + 3];
            float c0  = layer_b[l * 2 + 0],  c1  = layer_b[l * 2 + 1];
            float sc0 = layer_scale[l * 2 + 0], sc1 = layer_scale[l * 2 + 1];
            float t0  = layer_shift[l * 2 + 0], t1  = layer_shift[l * 2 + 1];
            float u0 = fast_tanh(fmaf(h0, w00, fmaf(h1, w01, c0)));
            float u1 = fast_tanh(fmaf(h0, w10, fmaf(h1, w11, c1)));
            h0 = fmaf(u0, sc0, t0);
            h1 = fmaf(u1, sc1, t1);
        }
        g_feats[n] = make_float2(h0, h1);
    }
}

// -------------------------------------------------------------------------
// Kernel 2: 128 blocks x 128 threads. One n per thread.
//   Coalesced column reduce (32 LDG.32, tid<49); g_feats load + trig ride
//   in the reduce's latency shadow; 7x2-float4 bilinear, MLP, softmax
//   (no max-sub; logits bounded).
// -------------------------------------------------------------------------
__global__ void __launch_bounds__(TPB) final_kernel(
    const float* __restrict__ W1,
    const float* __restrict__ b1,
    const float* __restrict__ W2,
    const float* __restrict__ b2,
    float* __restrict__ out)
{
    __shared__ __align__(16) float S[SPAD];   // 7 rows x 8 (pad col = 0)

    const int tid = threadIdx.x;
    const int n   = blockIdx.x * TPB + tid;

    // ---- coalesced column reduce: 32 LDG.32 per thread, 4 accumulators ----
    if (tid < R2) {
        const float* src = g_Spart + tid;
        float a0 = 0.f, a1 = 0.f, a2 = 0.f, a3 = 0.f;
        #pragma unroll
        for (int p = 0; p < PBLK; p += 4) {
            a0 += src[(p + 0) * EPAD];
            a1 += src[(p + 1) * EPAD];
            a2 += src[(p + 2) * EPAD];
            a3 += src[(p + 3) * EPAD];
        }
        int j = tid / RNK, k = tid - (tid / RNK) * RNK;
        S[j * RPAD + k] = (a0 + a1) + (a2 + a3);
    } else if (tid < R2 + RNK) {
        int j = tid - R2;                       // 7 pad slots (col 7)
        S[j * RPAD + (RPAD - 1)] = 0.0f;
    }

    // ---- feats load + trig features (overlap the reduce latency) ----
    float2 f = g_feats[n];
    float u0[RNK];
    __align__(16) float u1[RPAD];
    four_feats<false>(f.x, u0, 1.0f);
    four_feats<false>(f.y, u1, 1.0f);
    u1[RPAD - 1] = 0.0f;

    __syncthreads();

    // ---- bilinear form u0^T S u1 (7 rows x 2 float4) ----
    const float4* u1v = (const float4*)u1;
    float agg = 0.0f;
    #pragma unroll
    for (int j = 0; j < RNK; j++) {
        const float4* Sv = (const float4*)(S + j * RPAD);
        float4 s0 = Sv[0], s1 = Sv[1];
        float4 w0 = u1v[0], w1 = u1v[1];
        float t0 = fmaf(s0.x, w0.x, s1.x * w1.x);
        float t1 = fmaf(s0.y, w0.y, s1.y * w1.y);
        float t2 = fmaf(s0.z, w0.z, s1.z * w1.z);
        float t3 = fmaf(s0.w, w0.w, s1.w * w1.w);
        agg = fmaf(u0[j], (t0 + t1) + (t2 + t3), agg);
    }

    // ---- tiny MLP + 2-way softmax (logits bounded -> no max-sub) ----
    float hh[4];
    #pragma unroll
    for (int j = 0; j < 4; j++)
        hh[j] = fast_tanh(fmaf(agg, W1[j], b1[j]));

    float l0 = b2[0], l1 = b2[1];
    #pragma unroll
    for (int j = 0; j < 4; j++) {
        l0 = fmaf(W2[j],     hh[j], l0);
        l1 = fmaf(W2[4 + j], hh[j], l1);
    }

    const float LOG2E = 1.4426950408889634f;
    float e0 = ex2_approx(l0 * LOG2E);
    float e1 = ex2_approx(l1 * LOG2E);
    float inv = rcp_approx(e0 + e1);
    ((float2*)out)[n] = make_float2(e0 * inv, e1 * inv);
}

// -------------------------------------------------------------------------
extern "C" void kernel_launch(void* const* d_in, const int* in_sizes, int n_in,
                              void* d_out, int out_size)
{
    const float* x           = (const float*)d_in[0];
    const float* layer_W     = (const float*)d_in[1];
    const float* layer_b     = (const float*)d_in[2];
    const float* layer_scale = (const float*)d_in[3];
    const float* layer_shift = (const float*)d_in[4];
    const float* refset      = (const float*)d_in[5];
    const float* W1          = (const float*)d_in[6];
    const float* b1          = (const float*)d_in[7];
    const float* W2          = (const float*)d_in[8];
    const float* b2          = (const float*)d_in[9];
    float* out = (float*)d_out;

    prep_kernel<<<PBLK + FBLK, K1TPB>>>(refset, x, layer_W, layer_b,
                                        layer_scale, layer_shift);
    final_kernel<<<NBLK, TPB>>>(W1, b1, W2, b2, out);
}

// round 17
// speedup vs baseline: 1.2362x; 1.0037x over previous
#include <cuda_runtime.h>

// Problem constants
#define N_PTS   16384
#define M_REF   4096
#define L_LAYERS 8
#define KMAX    3                    // Fourier order; measured rel_err ~3.4e-6
#define RNK     (2*KMAX + 1)         // 7 features per coordinate
#define RPAD    8                    // padded row (2 x float4)
#define R2      (RNK*RNK)            // 49
#define SPAD    (RNK*RPAD)           // 56
#define EPAD    64                   // padded element stride (coalesced, pow2)
#define PBLK    32                   // producer blocks (S partials)
#define MPB     (M_REF / PBLK)       // 128 reference points per producer block
#define MGRP    4                    // m-groups per producer block
#define MSEG    (MPB / MGRP)         // 32 refs per group
#define K1TPB   256                  // kernel-1 block size
#define FBLK    (N_PTS / K1TPB)      // 64 feats blocks in kernel 1
#define TPB     128                  // kernel-2 block size
#define NBLK    (N_PTS / TPB)        // 128 kernel-2 blocks
#define SCALE   4.4711032452e-6f     // exp(-4) / 4096
#define TWOLOG2E 2.8853900817779268f // 2*log2(e)

// Scratch (device globals; fully rewritten every call)
// g_Spart layout [p][e]: producer block p's 49 S-elements (stride 64).
__device__ float  g_Spart[PBLK * EPAD];
__device__ float2 g_feats[N_PTS];

// c_0 = I_0(2), c_k = 2*I_k(2)
__constant__ float C_BES[KMAX + 1] = {
    2.27958530f, 3.18127371f, 1.37789690f, 0.42547992f
};

__device__ __forceinline__ float ex2_approx(float d) {
    float r; asm("ex2.approx.ftz.f32 %0, %1;" : "=f"(r) : "f"(d)); return r;
}
__device__ __forceinline__ float rcp_approx(float d) {
    float r; asm("rcp.approx.ftz.f32 %0, %1;" : "=f"(r) : "f"(d)); return r;
}
// tanh via e^{2x}: 1 - 2/(e^{2x}+1). Saturates correctly. Rel err ~1e-6.
__device__ __forceinline__ float fast_tanh(float x) {
    float e = ex2_approx(x * TWOLOG2E);
    return fmaf(-2.0f, rcp_approx(e + 1.0f), 1.0f);
}

// Fourier features via MUFU sin/cos + Chebyshev recurrence.
// out[0]=w0; out[k]=w_k cos(k a); out[KMAX+k]=w_k sin(k a), k=1..KMAX.
template <bool WEIGHTED>
__device__ __forceinline__ void four_feats(float ang, float* out, float wscale) {
    float s = __sinf(ang);
    float c = __cosf(ang);
    float c2 = 2.0f * c;
    float ckm = 1.0f, skm = 0.0f;
    float ck  = c,    sk  = s;
    out[0] = WEIGHTED ? C_BES[0] * wscale : 1.0f;
    #pragma unroll
    for (int k = 1; k <= KMAX; k++) {
        float w = WEIGHTED ? C_BES[k] * wscale : 1.0f;
        out[k]        = w * ck;
        out[KMAX + k] = w * sk;
        float cn = fmaf(c2, ck, -ckm);
        float sn = fmaf(c2, sk, -skm);
        ckm = ck; skm = sk; ck = cn; sk = sn;
    }
}

// -------------------------------------------------------------------------
// Kernel 1: 96 blocks x 256 threads, two disjoint roles:
//   blocks [0,32):   S-partial producers (128 refs each) -> g_Spart[b][*].
//                    Dot product parallelized over 4 m-groups (32 FMAs each)
//                    + 4-way smem combine (shortens the serial chain ~4x).
//   blocks [32,96):  8-layer tanh chain for 256 n's each -> g_feats.
//                    Constants folded: ex2 consumes pre-scaled weights, and
//                    tanh(y)*s+t = (t+s) - 2s*rcp(e+1).
// -------------------------------------------------------------------------
__global__ void __launch_bounds__(K1TPB) prep_kernel(
    const float* __restrict__ refset,
    const float* __restrict__ x,
    const float* __restrict__ layer_W,
    const float* __restrict__ layer_b,
    const float* __restrict__ layer_scale,
    const float* __restrict__ layer_shift)
{
    const int b   = blockIdx.x;
    const int tid = threadIdx.x;

    if (b < PBLK) {
        // ---------------- S-partial producer ----------------
        __shared__ __align__(16) float V0[MPB * RNK];
        __shared__ __align__(16) float V1[MPB * RNK];
        __shared__ __align__(16) float Spar[MGRP][SPAD];

        if (tid < MPB) {
            int m = b * MPB + tid;
            float2 g = ((const float2*)refset)[m];
            float v0[RNK], v1[RNK];
            four_feats<true>(g.x, v0, SCALE);   // e^-4/M folded into v0
            four_feats<true>(g.y, v1, 1.0f);
            #pragma unroll
            for (int i = 0; i < RNK; i++) {
                V0[tid * RNK + i] = v0[i];
                V1[tid * RNK + i] = v1[i];
            }
        }
        __syncthreads();

        // 4 m-groups x 64 threads (49 active each): 32 FMAs per thread
        {
            int e = tid & 63;
            int g = tid >> 6;
            if (e < R2) {
                int j = e / RNK, k = e - (e / RNK) * RNK;
                int base = g * MSEG;
                float a0 = 0.f, a1 = 0.f, a2 = 0.f, a3 = 0.f;
                #pragma unroll
                for (int mm = 0; mm < MSEG; mm += 4) {
                    a0 = fmaf(V0[(base + mm + 0) * RNK + j], V1[(base + mm + 0) * RNK + k], a0);
                    a1 = fmaf(V0[(base + mm + 1) * RNK + j], V1[(base + mm + 1) * RNK + k], a1);
                    a2 = fmaf(V0[(base + mm + 2) * RNK + j], V1[(base + mm + 2) * RNK + k], a2);
                    a3 = fmaf(V0[(base + mm + 3) * RNK + j], V1[(base + mm + 3) * RNK + k], a3);
                }
                Spar[g][e] = (a0 + a1) + (a2 + a3);
            }
        }
        __syncthreads();

        if (tid < R2) {
            // Coalesced row store: consecutive threads -> consecutive floats
            g_Spart[b * EPAD + tid] = (Spar[0][tid] + Spar[1][tid])
                                    + (Spar[2][tid] + Spar[3][tid]);
        }
    } else {
        // ---------------- tanh-chain feats (folded constants) ----------------
        int n = (b - PBLK) * K1TPB + tid;
        float2 xin = ((const float2*)x)[n];
        float h0 = xin.x, h1 = xin.y;
        #pragma unroll
        for (int l = 0; l < L_LAYERS; l++) {
            // Pre-scaled by 2*log2(e): ex2 consumes the linear output directly.
            float wk00 = layer_W[l * 4 + 0] * TWOLOG2E, wk01 = layer_W[l * 4 + 1] * TWOLOG2E;
            float wk10 = layer_W[l * 4 + 2] * TWOLOG2E, wk11 = layer_W[l * 4 + 3] * TWOLOG2E;
            float ck0  = layer_b[l * 2 + 0] * TWOLOG2E,  ck1  = layer_b[l * 2 + 1] * TWOLOG2E;
            float sc0 = layer_scale[l * 2 + 0], sc1 = layer_scale[l * 2 + 1];
            float t0  = layer_shift[l * 2 + 0], t1  = layer_shift[l * 2 + 1];
            float ts0 = t0 + sc0, ns0 = -2.0f * sc0;   // tanh*s+t = ts - 2s*rcp(e+1)
            float ts1 = t1 + sc1, ns1 = -2.0f * sc1;
            float e0 = ex2_approx(fmaf(h0, wk00, fmaf(h1, wk01, ck0)));
            float e1 = ex2_approx(fmaf(h0, wk10, fmaf(h1, wk11, ck1)));
            float r0 = rcp_approx(e0 + 1.0f);
            float r1 = rcp_approx(e1 + 1.0f);
            h0 = fmaf(ns0, r0, ts0);
            h1 = fmaf(ns1, r1, ts1);
        }
        g_feats[n] = make_float2(h0, h1);
    }
}

// -------------------------------------------------------------------------
// Kernel 2 (unchanged — measured best): 128 blocks x 128 threads.
//   Coalesced column reduce (32 LDG.32, tid<49); g_feats load + trig ride
//   in the reduce's latency shadow; 7x2-float4 bilinear, MLP, softmax
//   (no max-sub; logits bounded).
// -------------------------------------------------------------------------
__global__ void __launch_bounds__(TPB) final_kernel(
    const float* __restrict__ W1,
    const float* __restrict__ b1,
    const float* __restrict__ W2,
    const float* __restrict__ b2,
    float* __restrict__ out)
{
    __shared__ __align__(16) float S[SPAD];   // 7 rows x 8 (pad col = 0)

    const int tid = threadIdx.x;
    const int n   = blockIdx.x * TPB + tid;

    // ---- coalesced column reduce: 32 LDG.32 per thread, 4 accumulators ----
    if (tid < R2) {
        const float* src = g_Spart + tid;
        float a0 = 0.f, a1 = 0.f, a2 = 0.f, a3 = 0.f;
        #pragma unroll
        for (int p = 0; p < PBLK; p += 4) {
            a0 += src[(p + 0) * EPAD];
            a1 += src[(p + 1) * EPAD];
            a2 += src[(p + 2) * EPAD];
            a3 += src[(p + 3) * EPAD];
        }
        int j = tid / RNK, k = tid - (tid / RNK) * RNK;
        S[j * RPAD + k] = (a0 + a1) + (a2 + a3);
    } else if (tid < R2 + RNK) {
        int j = tid - R2;                       // 7 pad slots (col 7)
        S[j * RPAD + (RPAD - 1)] = 0.0f;
    }

    // ---- feats load + trig features (overlap the reduce latency) ----
    float2 f = g_feats[n];
    float u0[RNK];
    __align__(16) float u1[RPAD];
    four_feats<false>(f.x, u0, 1.0f);
    four_feats<false>(f.y, u1, 1.0f);
    u1[RPAD - 1] = 0.0f;

    __syncthreads();

    // ---- bilinear form u0^T S u1 (7 rows x 2 float4) ----
    const float4* u1v = (const float4*)u1;
    float agg = 0.0f;
    #pragma unroll
    for (int j = 0; j < RNK; j++) {
        const float4* Sv = (const float4*)(S + j * RPAD);
        float4 s0 = Sv[0], s1 = Sv[1];
        float4 w0 = u1v[0], w1 = u1v[1];
        float t0 = fmaf(s0.x, w0.x, s1.x * w1.x);
        float t1 = fmaf(s0.y, w0.y, s1.y * w1.y);
        float t2 = fmaf(s0.z, w0.z, s1.z * w1.z);
        float t3 = fmaf(s0.w, w0.w, s1.w * w1.w);
        agg = fmaf(u0[j], (t0 + t1) + (t2 + t3), agg);
    }

    // ---- tiny MLP + 2-way softmax (logits bounded -> no max-sub) ----
    float hh[4];
    #pragma unroll
    for (int j = 0; j < 4; j++)
        hh[j] = fast_tanh(fmaf(agg, W1[j], b1[j]));

    float l0 = b2[0], l1 = b2[1];
    #pragma unroll
    for (int j = 0; j < 4; j++) {
        l0 = fmaf(W2[j],     hh[j], l0);
        l1 = fmaf(W2[4 + j], hh[j], l1);
    }

    const float LOG2E = 1.4426950408889634f;
    float e0 = ex2_approx(l0 * LOG2E);
    float e1 = ex2_approx(l1 * LOG2E);
    float inv = rcp_approx(e0 + e1);
    ((float2*)out)[n] = make_float2(e0 * inv, e1 * inv);
}

// -------------------------------------------------------------------------
extern "C" void kernel_launch(void* const* d_in, const int* in_sizes, int n_in,
                              void* d_out, int out_size)
{
    const float* x           = (const float*)d_in[0];
    const float* layer_W     = (const float*)d_in[1];
    const float* layer_b     = (const float*)d_in[2];
    const float* layer_scale = (const float*)d_in[3];
    const float* layer_shift = (const float*)d_in[4];
    const float* refset      = (const float*)d_in[5];
    const float* W1          = (const float*)d_in[6];
    const float* b1          = (const float*)d_in[7];
    const float* W2          = (const float*)d_in[8];
    const float* b2          = (const float*)d_in[9];
    float* out = (float*)d_out;

    prep_kernel<<<PBLK + FBLK, K1TPB>>>(refset, x, layer_W, layer_b,
                                        layer_scale, layer_shift);
    final_kernel<<<NBLK, TPB>>>(W1, b1, W2, b2, out);
}